// round 4
// baseline (speedup 1.0000x reference)
#include <cuda_runtime.h>
#include <cstdint>

#define N_ROWS 131072
#define DIM 128
#define KCB 1024
#define BM 128
#define KC 128
#define XPITCH 132
#define PRECF 1e7f

// ---- device scratch (no allocations allowed) ----
__device__ int   g_ind[N_ROWS];
__device__ float g_esq[KCB];
__device__ float g_ET[DIM * KCB];       // quantized E transposed: [d][k]
__device__ float g_counts[KCB];
__device__ float g_sum[KCB * DIM];
__device__ float g_smoothed[KCB];

// exact replica of _qt: round(t*1e7)/1e7 in fp32, round-half-even, IEEE div
__device__ __forceinline__ float qt(float t) {
    return __fdiv_rn(rintf(__fmul_rn(t, PRECF)), PRECF);
}

// ---------------------------------------------------------------------------
// k_pre: quantize+transpose E, zero accumulators
// ---------------------------------------------------------------------------
__global__ void k_pre(const float* __restrict__ embed) {
    int k = blockIdx.x;
    int d = threadIdx.x;
    float e = embed[k * DIM + d];
    g_ET[d * KCB + k] = qt(e);
    g_sum[k * DIM + d] = 0.0f;
    if (d == 0) g_counts[k] = 0.0f;
}

// ---------------------------------------------------------------------------
// k_esq: XLA:GPU column-reduction emulation:
//   32 strided partials P_j = sum_{i=0..3} qt(e[j+32i])^2 (fused FMA),
//   then shfl-down-style pairwise tree combine.
// ---------------------------------------------------------------------------
__global__ void k_esq(const float* __restrict__ embed) {
    int k = blockIdx.x * 128 + threadIdx.x;
    const float* row = embed + (size_t)k * DIM;
    float s[32];
    #pragma unroll
    for (int j = 0; j < 32; j++) {
        float p = 0.0f;
        #pragma unroll
        for (int i = 0; i < 4; i++) {
            float e = qt(row[j + 32 * i]);
            p = __fmaf_rn(e, e, p);
        }
        s[j] = p;
    }
    #pragma unroll
    for (int off = 16; off; off >>= 1)
        #pragma unroll
        for (int t = 0; t < off; t++)
            s[t] = __fadd_rn(s[t], s[t + off]);
    g_esq[k] = qt(s[0]);
}

// ---------------------------------------------------------------------------
// k_main: fused GEMM (sequential-d fused FMA via f32x2) + exact-qt argmax
// grid = 1024 blocks (128 rows each), 256 threads, 8x8 micro-tile per thread
// ---------------------------------------------------------------------------
__global__ __launch_bounds__(256, 1)
void k_main(const float* __restrict__ x) {
    extern __shared__ float smem[];
    float* Xs    = smem;                      // [BM][XPITCH]
    float* Es    = smem + BM * XPITCH;        // [DIM][KC]
    float* esq_s = Es + DIM * KC;             // [KC]
    float* xsq_s = esq_s + KC;                // [BM]

    int tid = threadIdx.x;
    int tx = tid & 15;
    int ty = tid >> 4;
    int row0 = blockIdx.x * BM;

    for (int e = tid; e < BM * DIM / 4; e += 256) {
        int row = e >> 5, d4 = e & 31;
        float4 v = *(const float4*)(x + (size_t)(row0 + row) * DIM + d4 * 4);
        *(float4*)&Xs[row * XPITCH + d4 * 4] = v;
    }
    __syncthreads();

    // x_sq per row: XLA:GPU row-reduction emulation:
    // warp of 32 "lanes", vec=2, strided iters: lane t accumulates
    // {2t,2t+1} then {64+2t,64+2t+1} (fused FMA), lane-pair add,
    // then shfl-down pairwise tree. One thread emulates the whole warp.
    if (tid < BM) {
        const float* v = &Xs[tid * XPITCH];
        float s[32];
        #pragma unroll
        for (int t = 0; t < 32; t++) {
            float a0 = v[2 * t],      a1 = v[2 * t + 1];
            float b0 = v[64 + 2 * t], b1 = v[64 + 2 * t + 1];
            float p0 = __fmaf_rn(b0, b0, __fmaf_rn(a0, a0, 0.0f));
            float p1 = __fmaf_rn(b1, b1, __fmaf_rn(a1, a1, 0.0f));
            s[t] = __fadd_rn(p0, p1);
        }
        #pragma unroll
        for (int off = 16; off; off >>= 1)
            #pragma unroll
            for (int t = 0; t < off; t++)
                s[t] = __fadd_rn(s[t], s[t + off]);
        xsq_s[tid] = qt(s[0]);
    }

    float bestraw[8], bestex[8];
    int   bidx[8];
    #pragma unroll
    for (int i = 0; i < 8; i++) {
        bestraw[i] = -3.4e38f; bestex[i] = -3.4e38f; bidx[i] = 0;
    }

    for (int kc = 0; kc < KCB / KC; kc++) {
        __syncthreads();
        for (int e = tid; e < DIM * KC / 4; e += 256) {
            int d = e >> 5, k4 = e & 31;
            *(float4*)&Es[d * KC + k4 * 4] =
                *(const float4*)&g_ET[d * KCB + kc * KC + k4 * 4];
        }
        if (tid < KC) esq_s[tid] = g_esq[kc * KC + tid];
        __syncthreads();

        unsigned long long acc[8][4];
        #pragma unroll
        for (int i = 0; i < 8; i++)
            #pragma unroll
            for (int j = 0; j < 4; j++) acc[i][j] = 0ULL;

        #pragma unroll 2
        for (int d = 0; d < DIM; d += 4) {
            float4 a4[8];
            #pragma unroll
            for (int i = 0; i < 8; i++)
                a4[i] = *(float4*)&Xs[(ty * 8 + i) * XPITCH + d];
            #pragma unroll
            for (int dd = 0; dd < 4; dd++) {
                ulonglong2 b0 = *(ulonglong2*)&Es[(d + dd) * KC + tx * 8];
                ulonglong2 b1 = *(ulonglong2*)&Es[(d + dd) * KC + tx * 8 + 4];
                unsigned long long bp[4] = { b0.x, b0.y, b1.x, b1.y };
                #pragma unroll
                for (int i = 0; i < 8; i++) {
                    float a = (dd == 0) ? a4[i].x : (dd == 1) ? a4[i].y
                            : (dd == 2) ? a4[i].z : a4[i].w;
                    unsigned int au = __float_as_uint(a);
                    unsigned long long ap;
                    asm("mov.b64 %0, {%1, %1};" : "=l"(ap) : "r"(au));
                    #pragma unroll
                    for (int j = 0; j < 4; j++)
                        asm("fma.rn.f32x2 %0, %1, %2, %0;"
                            : "+l"(acc[i][j]) : "l"(ap), "l"(bp[j]));
                }
            }
        }

        // epilogue: raw screening + exact-qt chain for candidates
        #pragma unroll
        for (int i = 0; i < 8; i++) {
            float xsq = xsq_s[ty * 8 + i];
            #pragma unroll
            for (int j = 0; j < 4; j++) {
                unsigned int lo, hi;
                asm("mov.b64 {%0, %1}, %2;" : "=r"(lo), "=r"(hi) : "l"(acc[i][j]));
                int c = tx * 8 + 2 * j;
                #pragma unroll
                for (int h = 0; h < 2; h++) {
                    float dot = __uint_as_float(h ? hi : lo);
                    float esq = esq_s[c + h];
                    float raw = __fmaf_rn(2.0f, dot, -esq);
                    if (raw > bestraw[i]) bestraw[i] = raw;
                    if (raw >= bestraw[i] - 1e-3f) {
                        // dist = -qt( qt(x_sq+e_sq) - qt(qt(dot)*2) )
                        float c1 = qt(dot);
                        float c3 = qt(__fmul_rn(c1, 2.0f));
                        float S  = qt(__fadd_rn(xsq, esq));
                        float q  = qt(__fsub_rn(S, c3));
                        float dist = -q;
                        if (dist > bestex[i]) {          // ascending idx => first max
                            bestex[i] = dist;
                            bidx[i] = kc * KC + c + h;
                        }
                    }
                }
            }
        }
    }

    // cross-lane (16 lanes / row-group) reduce, ties -> lowest index
    #pragma unroll
    for (int i = 0; i < 8; i++) {
        for (int off = 8; off >= 1; off >>= 1) {
            float ov = __shfl_xor_sync(0xffffffffu, bestex[i], off);
            int   oi = __shfl_xor_sync(0xffffffffu, bidx[i], off);
            if (ov > bestex[i] || (ov == bestex[i] && oi < bidx[i])) {
                bestex[i] = ov; bidx[i] = oi;
            }
        }
    }
    if (tx == 0) {
        #pragma unroll
        for (int i = 0; i < 8; i++)
            g_ind[row0 + ty * 8 + i] = bidx[i];
    }
}

// ---------------------------------------------------------------------------
// k_scatter: quantize gather + raw segment-sum atomics + ind output
// ---------------------------------------------------------------------------
__global__ __launch_bounds__(256)
void k_scatter(const float* __restrict__ x,
               const float* __restrict__ embed,
               float* __restrict__ out_q,
               float* __restrict__ out_ind) {
    int w = (blockIdx.x * blockDim.x + threadIdx.x) >> 5;
    int lane = threadIdx.x & 31;
    int ind = g_ind[w];

    float4 e4 = ((const float4*)(embed + (size_t)ind * DIM))[lane];
    ((float4*)(out_q + (size_t)w * DIM))[lane] = e4;

    float4 x4 = ((const float4*)(x + (size_t)w * DIM))[lane];
    float* dst = g_sum + (size_t)ind * DIM + lane * 4;
    atomicAdd(dst + 0, x4.x);
    atomicAdd(dst + 1, x4.y);
    atomicAdd(dst + 2, x4.z);
    atomicAdd(dst + 3, x4.w);
    if (lane == 0) {
        atomicAdd(&g_counts[ind], 1.0f);
        out_ind[w] = (float)ind;
    }
}

// ---------------------------------------------------------------------------
// k_total: ncs = 0.99*cs + 0.01*counts; total; smoothed
// ---------------------------------------------------------------------------
__global__ void k_total(const float* __restrict__ cs, float* __restrict__ out_ncs) {
    __shared__ float ws[32];
    int tid = threadIdx.x;
    float v = __fadd_rn(__fmul_rn(cs[tid], 0.99f),
                        __fmul_rn(0.01f, g_counts[tid]));
    out_ncs[tid] = v;
    float s = v;
    #pragma unroll
    for (int off = 16; off; off >>= 1)
        s += __shfl_xor_sync(0xffffffffu, s, off);
    if ((tid & 31) == 0) ws[tid >> 5] = s;
    __syncthreads();
    if (tid < 32) {
        float t = ws[tid];
        #pragma unroll
        for (int off = 16; off; off >>= 1)
            t += __shfl_xor_sync(0xffffffffu, t, off);
        if (tid == 0) ws[0] = t;
    }
    __syncthreads();
    float total = ws[0];
    g_smoothed[tid] = __fmul_rn(
        __fdiv_rn(__fadd_rn(v, 1e-5f), __fadd_rn(total, 0.01024f)), total);
}

// ---------------------------------------------------------------------------
// k_embed: nea = 0.99*ea + 0.01*sum; ne = nea / smoothed[k]
// ---------------------------------------------------------------------------
__global__ void k_embed(const float* __restrict__ ea,
                        float* __restrict__ out_nea,
                        float* __restrict__ out_ne) {
    int i = (blockIdx.x * blockDim.x + threadIdx.x) * 4;
    float s = g_smoothed[i >> 7];
    float4 a = *(const float4*)&ea[i];
    float4 g = *(const float4*)&g_sum[i];
    float4 r, o;
    r.x = __fadd_rn(__fmul_rn(a.x, 0.99f), __fmul_rn(0.01f, g.x));
    r.y = __fadd_rn(__fmul_rn(a.y, 0.99f), __fmul_rn(0.01f, g.y));
    r.z = __fadd_rn(__fmul_rn(a.z, 0.99f), __fmul_rn(0.01f, g.z));
    r.w = __fadd_rn(__fmul_rn(a.w, 0.99f), __fmul_rn(0.01f, g.w));
    *(float4*)&out_nea[i] = r;
    o.x = __fdiv_rn(r.x, s); o.y = __fdiv_rn(r.y, s);
    o.z = __fdiv_rn(r.z, s); o.w = __fdiv_rn(r.w, s);
    *(float4*)&out_ne[i] = o;
}

// ---------------------------------------------------------------------------
extern "C" void kernel_launch(void* const* d_in, const int* in_sizes, int n_in,
                              void* d_out, int out_size) {
    const float* x     = (const float*)d_in[0];
    const float* embed = (const float*)d_in[1];
    const float* cs    = (const float*)d_in[2];
    const float* ea    = (const float*)d_in[3];

    float* out     = (float*)d_out;
    float* out_q   = out;                                  // 32*4096*128
    float* out_ind = out + (size_t)N_ROWS * DIM;           // 32*4096
    float* out_ncs = out_ind + N_ROWS;                     // 1024
    float* out_nea = out_ncs + KCB;                        // 1024*128
    float* out_ne  = out_nea + (size_t)KCB * DIM;          // 1024*128

    const int SMEM_BYTES = (BM * XPITCH + DIM * KC + KC + BM) * (int)sizeof(float);

    static bool attr_done = false;
    if (!attr_done) {
        cudaFuncSetAttribute(k_main, cudaFuncAttributeMaxDynamicSharedMemorySize,
                             SMEM_BYTES);
        attr_done = true;
    }

    k_pre<<<KCB, DIM>>>(embed);
    k_esq<<<KCB / 128, 128>>>(embed);
    k_main<<<N_ROWS / BM, 256, SMEM_BYTES>>>(x);
    k_scatter<<<(N_ROWS * 32) / 256, 256>>>(x, embed, out_q, out_ind);
    k_total<<<1, 1024>>>(cs, out_ncs);
    k_embed<<<(KCB * DIM) / (256 * 4), 256>>>(ea, out_nea, out_ne);
}

// round 5
// speedup vs baseline: 1.4847x; 1.4847x over previous
#include <cuda_runtime.h>
#include <cstdint>

#define N_ROWS 131072
#define DIM 128
#define KCB 1024
#define BM 128
#define KC 128
#define XPITCH 132
#define PRECF 1e7f
#define NCAND 16
#define MARGIN 1e-3f
#define FIXMARGIN 5e-4f

// ---- device scratch (no allocations allowed) ----
__device__ int   g_ind[N_ROWS];
__device__ float g_esq[KCB];
__device__ float g_Eq[KCB * DIM];       // quantized E, natural [k][d] layout
__device__ float g_xsq[N_ROWS];
__device__ int2  g_cand[(size_t)N_ROWS * NCAND];   // (raw_bits, idx)
__device__ int   g_ncand[N_ROWS];
__device__ float g_counts[KCB];
__device__ float g_sum[KCB * DIM];
__device__ float g_smoothed[KCB];

// exact replica of _qt: round(t*1e7)/1e7 in fp32, round-half-even, IEEE div
__device__ __forceinline__ float qt(float t) {
    return __fdiv_rn(rintf(__fmul_rn(t, PRECF)), PRECF);
}

__device__ __forceinline__ void cp16(uint32_t dst_smem, const void* src) {
    asm volatile("cp.async.cg.shared.global [%0], [%1], 16;"
                 :: "r"(dst_smem), "l"(src));
}
__device__ __forceinline__ void cp_commit() {
    asm volatile("cp.async.commit_group;");
}
template <int N>
__device__ __forceinline__ void cp_wait() {
    asm volatile("cp.async.wait_group %0;" :: "n"(N));
}

// ---------------------------------------------------------------------------
// k_pre: quantize E (natural layout), zero accumulators
// ---------------------------------------------------------------------------
__global__ void k_pre(const float* __restrict__ embed) {
    int k = blockIdx.x;
    int d = threadIdx.x;
    g_Eq[k * DIM + d] = qt(embed[k * DIM + d]);
    g_sum[k * DIM + d] = 0.0f;
    if (d == 0) g_counts[k] = 0.0f;
}

// ---------------------------------------------------------------------------
// k_esq: XLA:GPU column-reduction emulation (proven bit-exact in R4)
// ---------------------------------------------------------------------------
__global__ void k_esq(const float* __restrict__ embed) {
    int k = blockIdx.x * 128 + threadIdx.x;
    const float* row = embed + (size_t)k * DIM;
    float s[32];
    #pragma unroll
    for (int j = 0; j < 32; j++) {
        float p = 0.0f;
        #pragma unroll
        for (int i = 0; i < 4; i++) {
            float e = qt(row[j + 32 * i]);
            p = __fmaf_rn(e, e, p);
        }
        s[j] = p;
    }
    #pragma unroll
    for (int off = 16; off; off >>= 1)
        #pragma unroll
        for (int t = 0; t < off; t++)
            s[t] = __fadd_rn(s[t], s[t + off]);
    g_esq[k] = qt(s[0]);
}

// ---------------------------------------------------------------------------
// k_main: screening GEMM. f32x2 packs (even d, odd d) -> no dup movs.
// 512 threads: warp w owns rows w*8..w*8+7; lane owns codes lane*4..lane*4+3
// per chunk. E chunks double-buffered via cp.async, XOR-swizzled by (c>>2).
// Emits per-row candidate lists (raw, idx); exact decision deferred to k_fix.
// ---------------------------------------------------------------------------
__global__ __launch_bounds__(512, 1)
void k_main(const float* __restrict__ x) {
    extern __shared__ float smem[];
    float* Es    = smem;                       // 2 x [128][128] swizzled
    float* Xs    = smem + 2 * KC * DIM;        // [BM][XPITCH]
    float* esq_s = Xs + BM * XPITCH;           // [1024]
    int*   cnt_s = (int*)(esq_s + KCB);        // [BM]

    int tid  = threadIdx.x;
    int warp = tid >> 5;
    int lane = tid & 31;
    int lane4 = lane * 4;
    int rowb = warp * 8;
    int row0 = blockIdx.x * BM;

    if (tid < BM) cnt_s[tid] = 0;

    // prefetch E chunk 0 (swizzled store: granule g of code c -> g ^ (c>>2))
    {
        uint32_t base = (uint32_t)__cvta_generic_to_shared(Es);
        #pragma unroll
        for (int s = 0; s < 8; s++) {
            int idx = tid + s * 512;           // 4096 granules
            int c = idx >> 5, g = idx & 31;
            cp16(base + (uint32_t)(c * 512 + ((g ^ ((c >> 2) & 31)) << 4)),
                 g_Eq + (size_t)c * DIM + g * 4);
        }
        cp_commit();
    }

    // load X tile + esq table
    for (int e = tid; e < BM * DIM / 4; e += 512) {
        int row = e >> 5, d4 = e & 31;
        float4 v = *(const float4*)(x + (size_t)(row0 + row) * DIM + d4 * 4);
        *(float4*)&Xs[row * XPITCH + d4 * 4] = v;
    }
    if (tid < 512) {
        esq_s[tid] = g_esq[tid];
        esq_s[tid + 512] = g_esq[tid + 512];
    }
    __syncthreads();

    // x_sq per row: XLA:GPU row-reduction emulation (proven bit-exact in R4)
    if (tid < BM) {
        const float* v = &Xs[tid * XPITCH];
        float s[32];
        #pragma unroll
        for (int t = 0; t < 32; t++) {
            float a0 = v[2 * t],      a1 = v[2 * t + 1];
            float b0 = v[64 + 2 * t], b1 = v[64 + 2 * t + 1];
            float p0 = __fmaf_rn(b0, b0, __fmaf_rn(a0, a0, 0.0f));
            float p1 = __fmaf_rn(b1, b1, __fmaf_rn(a1, a1, 0.0f));
            s[t] = __fadd_rn(p0, p1);
        }
        #pragma unroll
        for (int off = 16; off; off >>= 1)
            #pragma unroll
            for (int t = 0; t < off; t++)
                s[t] = __fadd_rn(s[t], s[t + off]);
        g_xsq[row0 + tid] = qt(s[0]);
    }

    float wbest[8];
    #pragma unroll
    for (int i = 0; i < 8; i++) wbest[i] = -3.4e38f;

    for (int kc = 0; kc < KCB / KC; kc++) {
        float* Eb = Es + (kc & 1) * KC * DIM;
        // prefetch next chunk into the other buffer
        if (kc + 1 < KCB / KC) {
            float* En = Es + ((kc + 1) & 1) * KC * DIM;
            uint32_t base = (uint32_t)__cvta_generic_to_shared(En);
            #pragma unroll
            for (int s = 0; s < 8; s++) {
                int idx = tid + s * 512;
                int c = idx >> 5, g = idx & 31;
                cp16(base + (uint32_t)(c * 512 + ((g ^ ((c >> 2) & 31)) << 4)),
                     g_Eq + (size_t)(kc + 1) * KC * DIM + (size_t)c * DIM + g * 4);
            }
            cp_commit();
            cp_wait<1>();
        } else {
            cp_wait<0>();
        }
        __syncthreads();

        unsigned long long acc[8][4];
        #pragma unroll
        for (int i = 0; i < 8; i++)
            #pragma unroll
            for (int j = 0; j < 4; j++) acc[i][j] = 0ULL;

        #pragma unroll 4
        for (int d = 0; d < DIM; d += 4) {
            int g = d >> 2;
            ulonglong2 b[4];
            #pragma unroll
            for (int j = 0; j < 4; j++)
                b[j] = *(ulonglong2*)&Eb[(lane4 + j) * DIM + ((g ^ lane) << 2)];
            #pragma unroll
            for (int i = 0; i < 8; i++) {
                ulonglong2 a = *(ulonglong2*)&Xs[(rowb + i) * XPITCH + d];
                #pragma unroll
                for (int j = 0; j < 4; j++) {
                    asm("fma.rn.f32x2 %0, %1, %2, %0;"
                        : "+l"(acc[i][j]) : "l"(a.x), "l"(b[j].x));
                    asm("fma.rn.f32x2 %0, %1, %2, %0;"
                        : "+l"(acc[i][j]) : "l"(a.y), "l"(b[j].y));
                }
            }
        }

        // epilogue: raw scores, warp running max, candidate collection
        #pragma unroll
        for (int i = 0; i < 8; i++) {
            float raw[4];
            float m = -3.4e38f;
            #pragma unroll
            for (int j = 0; j < 4; j++) {
                unsigned int lo, hi;
                asm("mov.b64 {%0, %1}, %2;" : "=r"(lo), "=r"(hi) : "l"(acc[i][j]));
                float dot = __fadd_rn(__uint_as_float(lo), __uint_as_float(hi));
                raw[j] = __fmaf_rn(2.0f, dot, -esq_s[kc * KC + lane4 + j]);
                m = fmaxf(m, raw[j]);
            }
            #pragma unroll
            for (int off = 16; off; off >>= 1)
                m = fmaxf(m, __shfl_xor_sync(0xffffffffu, m, off));
            float nb = fmaxf(wbest[i], m);
            wbest[i] = nb;
            float thr = nb - MARGIN;
            #pragma unroll
            for (int j = 0; j < 4; j++) {
                if (raw[j] >= thr) {
                    int slot = atomicAdd(&cnt_s[rowb + i], 1);
                    if (slot < NCAND)
                        g_cand[(size_t)(row0 + rowb + i) * NCAND + slot] =
                            make_int2(__float_as_int(raw[j]), kc * KC + lane4 + j);
                }
            }
        }
        __syncthreads();
    }

    if (tid < BM) {
        int n = cnt_s[tid];
        g_ncand[row0 + tid] = n < NCAND ? n : NCAND;
    }
}

// ---------------------------------------------------------------------------
// k_fix: per-row final decision. Single qualifier -> done; else exact
// sequential-k dot + exact-qt chain (bit-identical to R4 logic), tie->low idx.
// ---------------------------------------------------------------------------
__global__ void k_fix(const float* __restrict__ x) {
    int row = blockIdx.x * 256 + threadIdx.x;
    int n = g_ncand[row];
    const int2* cand = &g_cand[(size_t)row * NCAND];

    float mr = -3.4e38f;
    for (int s = 0; s < n; s++)
        mr = fmaxf(mr, __int_as_float(cand[s].x));
    float thr = mr - FIXMARGIN;

    int nq = 0, only = 0;
    for (int s = 0; s < n; s++)
        if (__int_as_float(cand[s].x) >= thr) { nq++; only = cand[s].y; }

    if (nq <= 1) { g_ind[row] = only; return; }

    float xsq = g_xsq[row];
    const float* xr = x + (size_t)row * DIM;
    float bd = -3.4e38f;
    int   bi = 0x7FFFFFFF;
    for (int s = 0; s < n; s++) {
        if (__int_as_float(cand[s].x) < thr) continue;
        int c = cand[s].y;
        const float* e = g_Eq + (size_t)c * DIM;
        float dot = 0.0f;
        for (int d = 0; d < DIM; d++)
            dot = __fmaf_rn(xr[d], e[d], dot);
        float c1 = qt(dot);
        float c3 = qt(__fmul_rn(c1, 2.0f));
        float S  = qt(__fadd_rn(xsq, g_esq[c]));
        float q  = qt(__fsub_rn(S, c3));
        float dist = -q;
        if (dist > bd || (dist == bd && c < bi)) { bd = dist; bi = c; }
    }
    g_ind[row] = bi;
}

// ---------------------------------------------------------------------------
// k_scatter: quantize gather + raw segment-sum atomics + ind output
// ---------------------------------------------------------------------------
__global__ __launch_bounds__(256)
void k_scatter(const float* __restrict__ x,
               const float* __restrict__ embed,
               float* __restrict__ out_q,
               float* __restrict__ out_ind) {
    int w = (blockIdx.x * blockDim.x + threadIdx.x) >> 5;
    int lane = threadIdx.x & 31;
    int ind = g_ind[w];

    float4 e4 = ((const float4*)(embed + (size_t)ind * DIM))[lane];
    ((float4*)(out_q + (size_t)w * DIM))[lane] = e4;

    float4 x4 = ((const float4*)(x + (size_t)w * DIM))[lane];
    float* dst = g_sum + (size_t)ind * DIM + lane * 4;
    atomicAdd(dst + 0, x4.x);
    atomicAdd(dst + 1, x4.y);
    atomicAdd(dst + 2, x4.z);
    atomicAdd(dst + 3, x4.w);
    if (lane == 0) {
        atomicAdd(&g_counts[ind], 1.0f);
        out_ind[w] = (float)ind;
    }
}

// ---------------------------------------------------------------------------
// k_total: ncs = 0.99*cs + 0.01*counts; total; smoothed
// ---------------------------------------------------------------------------
__global__ void k_total(const float* __restrict__ cs, float* __restrict__ out_ncs) {
    __shared__ float ws[32];
    int tid = threadIdx.x;
    float v = __fadd_rn(__fmul_rn(cs[tid], 0.99f),
                        __fmul_rn(0.01f, g_counts[tid]));
    out_ncs[tid] = v;
    float s = v;
    #pragma unroll
    for (int off = 16; off; off >>= 1)
        s += __shfl_xor_sync(0xffffffffu, s, off);
    if ((tid & 31) == 0) ws[tid >> 5] = s;
    __syncthreads();
    if (tid < 32) {
        float t = ws[tid];
        #pragma unroll
        for (int off = 16; off; off >>= 1)
            t += __shfl_xor_sync(0xffffffffu, t, off);
        if (tid == 0) ws[0] = t;
    }
    __syncthreads();
    float total = ws[0];
    g_smoothed[tid] = __fmul_rn(
        __fdiv_rn(__fadd_rn(v, 1e-5f), __fadd_rn(total, 0.01024f)), total);
}

// ---------------------------------------------------------------------------
// k_embed: nea = 0.99*ea + 0.01*sum; ne = nea / smoothed[k]
// ---------------------------------------------------------------------------
__global__ void k_embed(const float* __restrict__ ea,
                        float* __restrict__ out_nea,
                        float* __restrict__ out_ne) {
    int i = (blockIdx.x * blockDim.x + threadIdx.x) * 4;
    float s = g_smoothed[i >> 7];
    float4 a = *(const float4*)&ea[i];
    float4 g = *(const float4*)&g_sum[i];
    float4 r, o;
    r.x = __fadd_rn(__fmul_rn(a.x, 0.99f), __fmul_rn(0.01f, g.x));
    r.y = __fadd_rn(__fmul_rn(a.y, 0.99f), __fmul_rn(0.01f, g.y));
    r.z = __fadd_rn(__fmul_rn(a.z, 0.99f), __fmul_rn(0.01f, g.z));
    r.w = __fadd_rn(__fmul_rn(a.w, 0.99f), __fmul_rn(0.01f, g.w));
    *(float4*)&out_nea[i] = r;
    o.x = __fdiv_rn(r.x, s); o.y = __fdiv_rn(r.y, s);
    o.z = __fdiv_rn(r.z, s); o.w = __fdiv_rn(r.w, s);
    *(float4*)&out_ne[i] = o;
}

// ---------------------------------------------------------------------------
extern "C" void kernel_launch(void* const* d_in, const int* in_sizes, int n_in,
                              void* d_out, int out_size) {
    const float* x     = (const float*)d_in[0];
    const float* embed = (const float*)d_in[1];
    const float* cs    = (const float*)d_in[2];
    const float* ea    = (const float*)d_in[3];

    float* out     = (float*)d_out;
    float* out_q   = out;                                  // 32*4096*128
    float* out_ind = out + (size_t)N_ROWS * DIM;           // 32*4096
    float* out_ncs = out_ind + N_ROWS;                     // 1024
    float* out_nea = out_ncs + KCB;                        // 1024*128
    float* out_ne  = out_nea + (size_t)KCB * DIM;          // 1024*128

    const int SMEM_BYTES =
        (2 * KC * DIM + BM * XPITCH + KCB + BM) * (int)sizeof(float);

    static bool attr_done = false;
    if (!attr_done) {
        cudaFuncSetAttribute(k_main, cudaFuncAttributeMaxDynamicSharedMemorySize,
                             SMEM_BYTES);
        attr_done = true;
    }

    k_pre<<<KCB, DIM>>>(embed);
    k_esq<<<KCB / 128, 128>>>(embed);
    k_main<<<N_ROWS / BM, 512, SMEM_BYTES>>>(x);
    k_fix<<<N_ROWS / 256, 256>>>(x);
    k_scatter<<<(N_ROWS * 32) / 256, 256>>>(x, embed, out_q, out_ind);
    k_total<<<1, 1024>>>(cs, out_ncs);
    k_embed<<<(KCB * DIM) / (256 * 4), 256>>>(ea, out_nea, out_ne);
}

// round 7
// speedup vs baseline: 3.4058x; 2.2940x over previous
#include <cuda_runtime.h>
#include <cuda_bf16.h>
#include <cstdint>

#define N_ROWS 131072
#define DIM 128
#define KCB 1024
#define BM 128
#define PRECF 1e7f
#define NCAND 16
#define MARGIN 2e-3f
#define FIXMARGIN 1e-3f

// padded row: 128 bf16 = 256B + 16B pad = 272B  (272 mod 128 = 16 -> ldmatrix
// addresses of 8 consecutive rows hit 8 distinct 16B banks, conflict-free)
#define ROWB 272
#define TILEB (BM * ROWB)          // 34816 bytes: one 128x128 bf16 tile
#define CHUNKB (2 * TILEB)         // 69632: hi tile + lo tile

// smem layout
#define SM_XH  0
#define SM_XL  TILEB
#define SM_E   (2 * TILEB)                 // + buf*CHUNKB, 2 buffers
#define SM_ESQ (2 * TILEB + 2 * CHUNKB)    // 208896, 1024 floats
#define SM_CNT (SM_ESQ + 4096)             // 212992, 128 ints
#define SMEM_BYTES (SM_CNT + 512)          // 213504

// ---- device scratch ----
__device__ int     g_ind[N_ROWS];
__device__ float   g_esq[KCB];
__device__ float   g_Eq[KCB * DIM];          // qt(E), natural layout (k_fix)
__device__ uint8_t g_Esw[8 * CHUNKB];        // per chunk: [hi tile][lo tile], padded
__device__ int2    g_cand[(size_t)N_ROWS * NCAND];
__device__ int     g_ncand[N_ROWS];
__device__ float   g_counts[KCB];
__device__ float   g_sum[KCB * DIM];
__device__ float   g_smoothed[KCB];

__device__ __forceinline__ float qt(float t) {
    return __fdiv_rn(rintf(__fmul_rn(t, PRECF)), PRECF);
}
__device__ __forceinline__ uint32_t smem_u32(const void* p) {
    return (uint32_t)__cvta_generic_to_shared(p);
}
__device__ __forceinline__ void cp16(uint32_t dst, const void* src) {
    asm volatile("cp.async.cg.shared.global [%0], [%1], 16;" :: "r"(dst), "l"(src));
}
__device__ __forceinline__ void cp_commit() { asm volatile("cp.async.commit_group;"); }
template <int N>
__device__ __forceinline__ void cp_wait() {
    asm volatile("cp.async.wait_group %0;" :: "n"(N));
}
__device__ __forceinline__ void ldsm4(uint32_t* r, uint32_t addr) {
    asm volatile("ldmatrix.sync.aligned.m8n8.x4.shared.b16 {%0,%1,%2,%3},[%4];"
                 : "=r"(r[0]), "=r"(r[1]), "=r"(r[2]), "=r"(r[3]) : "r"(addr));
}
__device__ __forceinline__ void mma_bf16(float* d, const uint32_t* a,
                                         uint32_t b0, uint32_t b1) {
    asm volatile(
        "mma.sync.aligned.m16n8k16.row.col.f32.bf16.bf16.f32 "
        "{%0,%1,%2,%3},{%4,%5,%6,%7},{%8,%9},{%0,%1,%2,%3};"
        : "+f"(d[0]), "+f"(d[1]), "+f"(d[2]), "+f"(d[3])
        : "r"(a[0]), "r"(a[1]), "r"(a[2]), "r"(a[3]), "r"(b0), "r"(b1));
}

// exact R4 GPU-shape x_sq over one 128-float row
__device__ float xsq_row(const float* __restrict__ v) {
    float s[32];
    #pragma unroll
    for (int t = 0; t < 32; t++) {
        float a0 = v[2 * t], a1 = v[2 * t + 1];
        float b0 = v[64 + 2 * t], b1 = v[64 + 2 * t + 1];
        float p0 = __fmaf_rn(b0, b0, __fmaf_rn(a0, a0, 0.0f));
        float p1 = __fmaf_rn(b1, b1, __fmaf_rn(a1, a1, 0.0f));
        s[t] = __fadd_rn(p0, p1);
    }
    #pragma unroll
    for (int off = 16; off; off >>= 1)
        #pragma unroll
        for (int t = 0; t < off; t++)
            s[t] = __fadd_rn(s[t], s[t + off]);
    return qt(s[0]);
}

// ---------------------------------------------------------------------------
// k_pre: qt(E); bf16 hi/lo split into padded chunk tiles; zero accums
// ---------------------------------------------------------------------------
__global__ void k_pre(const float* __restrict__ embed) {
    int k = blockIdx.x;
    int d = threadIdx.x;
    float eq = qt(embed[k * DIM + d]);
    g_Eq[k * DIM + d] = eq;
    __nv_bfloat16 hi = __float2bfloat16(eq);
    __nv_bfloat16 lo = __float2bfloat16(__fsub_rn(eq, __bfloat162float(hi)));
    int chunk = k >> 7, c = k & 127;
    uint8_t* base = g_Esw + (size_t)chunk * CHUNKB + c * ROWB + d * 2;
    *(__nv_bfloat16*)base = hi;
    *(__nv_bfloat16*)(base + TILEB) = lo;
    g_sum[k * DIM + d] = 0.0f;
    if (d == 0) g_counts[k] = 0.0f;
}

// ---------------------------------------------------------------------------
// k_esq: XLA:GPU column-reduction emulation (bit-exact, proven R4)
// ---------------------------------------------------------------------------
__global__ void k_esq(const float* __restrict__ embed) {
    int k = blockIdx.x * 128 + threadIdx.x;
    const float* row = embed + (size_t)k * DIM;
    float s[32];
    #pragma unroll
    for (int j = 0; j < 32; j++) {
        float p = 0.0f;
        #pragma unroll
        for (int i = 0; i < 4; i++) {
            float e = qt(row[j + 32 * i]);
            p = __fmaf_rn(e, e, p);
        }
        s[j] = p;
    }
    #pragma unroll
    for (int off = 16; off; off >>= 1)
        #pragma unroll
        for (int t = 0; t < off; t++)
            s[t] = __fadd_rn(s[t], s[t + off]);
    g_esq[k] = qt(s[0]);
}

// ---------------------------------------------------------------------------
// k_main: HMMA bf16 3-term split GEMM screen + in-register argmax
// 256 threads = 8 warps, warp w owns rows w*16..w*16+15 x all codes
// ---------------------------------------------------------------------------
__global__ __launch_bounds__(256, 1)
void k_main(const float* __restrict__ x) {
    extern __shared__ char smem[];
    uint32_t sb = smem_u32(smem);
    float* esq_s = (float*)(smem + SM_ESQ);
    int*   cnt_s = (int*)(smem + SM_CNT);

    int tid = threadIdx.x;
    int warp = tid >> 5;
    int lane = tid & 31;
    int g = lane >> 2, tig = lane & 3;
    int row0 = blockIdx.x * BM;

    if (tid < BM) cnt_s[tid] = 0;

    // prefetch E chunks 0 and 1 (one commit group each)
    #pragma unroll
    for (int b = 0; b < 2; b++) {
        #pragma unroll
        for (int s = 0; s < 17; s++) {
            int gr = tid + s * 256;            // 4352 granules of 16B
            cp16(sb + SM_E + b * CHUNKB + gr * 16,
                 g_Esw + (size_t)b * CHUNKB + gr * 16);
        }
        cp_commit();
    }

    // X load + bf16 hi/lo split into padded tiles
    #pragma unroll
    for (int s = 0; s < 32; s++) {
        int p = tid + s * 256;                 // 8192 pairs
        int row = p >> 6, d = (p & 63) * 2;
        float2 v = *(const float2*)(x + (size_t)(row0 + row) * DIM + d);
        __nv_bfloat16 h0 = __float2bfloat16(v.x);
        __nv_bfloat16 h1 = __float2bfloat16(v.y);
        __nv_bfloat16 l0 = __float2bfloat16(__fsub_rn(v.x, __bfloat162float(h0)));
        __nv_bfloat16 l1 = __float2bfloat16(__fsub_rn(v.y, __bfloat162float(h1)));
        *(__nv_bfloat162*)(smem + SM_XH + row * ROWB + d * 2) = __nv_bfloat162(h0, h1);
        *(__nv_bfloat162*)(smem + SM_XL + row * ROWB + d * 2) = __nv_bfloat162(l0, l1);
    }
    #pragma unroll
    for (int s = 0; s < 4; s++) esq_s[tid + s * 256] = g_esq[tid + s * 256];
    __syncthreads();

    // A fragments (X hi/lo), resident for all chunks: 8 ksteps x 4 regs each
    uint32_t ah[8][4], al[8][4];
    {
        uint32_t abase = sb + SM_XH + (warp * 16 + (lane & 15)) * ROWB
                       + (lane >> 4) * 16;
        #pragma unroll
        for (int s = 0; s < 8; s++) {
            ldsm4(ah[s], abase + s * 32);
            ldsm4(al[s], abase + TILEB + s * 32);
        }
    }

    float bestA = -3.4e38f, bestB = -3.4e38f;
    int rowA = warp * 16 + g, rowB = rowA + 8;

    for (int kc = 0; kc < 8; kc++) {
        if (kc < 7) cp_wait<1>(); else cp_wait<0>();
        __syncthreads();
        uint32_t eb = sb + SM_E + (kc & 1) * CHUNKB;

        #pragma unroll
        for (int h = 0; h < 2; h++) {          // 64 codes per half
            float acc[8][4];
            #pragma unroll
            for (int n = 0; n < 8; n++)
                #pragma unroll
                for (int j = 0; j < 4; j++) acc[n][j] = 0.0f;

            #pragma unroll
            for (int pp = 0; pp < 2; pp++) {   // 32-code block: 4 ntiles
                int nt0 = pp * 4;
                uint32_t b0a = eb + (uint32_t)((h * 64 + pp * 32 + (lane & 7)
                                 + ((lane & 16) ? 8 : 0)) * ROWB)
                             + ((lane >> 3) & 1) * 16;
                uint32_t b1a = b0a + 16 * ROWB;
                // hi-E phase: a_hi + a_lo terms
                #pragma unroll
                for (int s = 0; s < 8; s++) {
                    uint32_t bh0[4], bh1[4];
                    ldsm4(bh0, b0a + s * 32);
                    ldsm4(bh1, b1a + s * 32);
                    mma_bf16(acc[nt0 + 0], ah[s], bh0[0], bh0[1]);
                    mma_bf16(acc[nt0 + 1], ah[s], bh0[2], bh0[3]);
                    mma_bf16(acc[nt0 + 2], ah[s], bh1[0], bh1[1]);
                    mma_bf16(acc[nt0 + 3], ah[s], bh1[2], bh1[3]);
                    mma_bf16(acc[nt0 + 0], al[s], bh0[0], bh0[1]);
                    mma_bf16(acc[nt0 + 1], al[s], bh0[2], bh0[3]);
                    mma_bf16(acc[nt0 + 2], al[s], bh1[0], bh1[1]);
                    mma_bf16(acc[nt0 + 3], al[s], bh1[2], bh1[3]);
                }
                // lo-E phase: a_hi term only
                #pragma unroll
                for (int s = 0; s < 8; s++) {
                    uint32_t bl0[4], bl1[4];
                    ldsm4(bl0, b0a + TILEB + s * 32);
                    ldsm4(bl1, b1a + TILEB + s * 32);
                    mma_bf16(acc[nt0 + 0], ah[s], bl0[0], bl0[1]);
                    mma_bf16(acc[nt0 + 1], ah[s], bl0[2], bl0[3]);
                    mma_bf16(acc[nt0 + 2], ah[s], bl1[0], bl1[1]);
                    mma_bf16(acc[nt0 + 3], ah[s], bl1[2], bl1[3]);
                }
            }

            // epilogue: scores in-place, row max, candidate collection
            float mA = -3.4e38f, mB = -3.4e38f;
            #pragma unroll
            for (int nt = 0; nt < 8; nt++) {
                int c = kc * 128 + h * 64 + nt * 8 + tig * 2;
                float e0 = esq_s[c], e1 = esq_s[c + 1];
                acc[nt][0] = __fmaf_rn(2.0f, acc[nt][0], -e0);
                acc[nt][1] = __fmaf_rn(2.0f, acc[nt][1], -e1);
                acc[nt][2] = __fmaf_rn(2.0f, acc[nt][2], -e0);
                acc[nt][3] = __fmaf_rn(2.0f, acc[nt][3], -e1);
                mA = fmaxf(mA, fmaxf(acc[nt][0], acc[nt][1]));
                mB = fmaxf(mB, fmaxf(acc[nt][2], acc[nt][3]));
            }
            mA = fmaxf(mA, __shfl_xor_sync(0xffffffffu, mA, 1));
            mA = fmaxf(mA, __shfl_xor_sync(0xffffffffu, mA, 2));
            mB = fmaxf(mB, __shfl_xor_sync(0xffffffffu, mB, 1));
            mB = fmaxf(mB, __shfl_xor_sync(0xffffffffu, mB, 2));
            bestA = fmaxf(bestA, mA);
            bestB = fmaxf(bestB, mB);
            float thrA = bestA - MARGIN, thrB = bestB - MARGIN;

            #pragma unroll
            for (int nt = 0; nt < 8; nt++) {
                int c = kc * 128 + h * 64 + nt * 8 + tig * 2;
                #pragma unroll
                for (int j = 0; j < 4; j++) {
                    float sc = acc[nt][j];
                    bool isB = (j >= 2);
                    if (sc >= (isB ? thrB : thrA)) {
                        int r = isB ? rowB : rowA;
                        int slot = atomicAdd(&cnt_s[r], 1);
                        if (slot < NCAND)
                            g_cand[(size_t)(row0 + r) * NCAND + slot] =
                                make_int2(__float_as_int(sc), c + (j & 1));
                    }
                }
            }
        }

        __syncthreads();   // all warps done reading E buffer (kc&1)
        if (kc + 2 < 8) {
            #pragma unroll
            for (int s = 0; s < 17; s++) {
                int gr = tid + s * 256;
                cp16(sb + SM_E + (kc & 1) * CHUNKB + gr * 16,
                     g_Esw + (size_t)(kc + 2) * CHUNKB + gr * 16);
            }
            cp_commit();
        }
    }

    __syncthreads();
    if (tid < BM) g_ncand[row0 + tid] = cnt_s[tid];
}

// ---------------------------------------------------------------------------
// k_fix: final decision. 1 qualifier -> done; else bit-exact R4 chain.
// Overflowed candidate list -> full exact scan.
// ---------------------------------------------------------------------------
__global__ void k_fix(const float* __restrict__ x) {
    int row = blockIdx.x * 256 + threadIdx.x;
    int n = g_ncand[row];
    const float* xr = x + (size_t)row * DIM;

    if (n <= NCAND) {
        const int2* cand = &g_cand[(size_t)row * NCAND];
        float mr = -3.4e38f;
        for (int s = 0; s < n; s++)
            mr = fmaxf(mr, __int_as_float(cand[s].x));
        float thr = mr - FIXMARGIN;

        int nq = 0, only = 0;
        for (int s = 0; s < n; s++)
            if (__int_as_float(cand[s].x) >= thr) { nq++; only = cand[s].y; }
        if (nq <= 1) { g_ind[row] = only; return; }

        float xsq = xsq_row(xr);
        float bd = -3.4e38f;
        int bi = 0x7FFFFFFF;
        for (int s = 0; s < n; s++) {
            if (__int_as_float(cand[s].x) < thr) continue;
            int c = cand[s].y;
            const float* e = g_Eq + (size_t)c * DIM;
            float dot = 0.0f;
            for (int d = 0; d < DIM; d++)
                dot = __fmaf_rn(xr[d], e[d], dot);
            float c3 = qt(__fmul_rn(qt(dot), 2.0f));
            float S  = qt(__fadd_rn(xsq, g_esq[c]));
            float dist = -qt(__fsub_rn(S, c3));
            if (dist > bd || (dist == bd && c < bi)) { bd = dist; bi = c; }
        }
        g_ind[row] = bi;
    } else {
        float xsq = xsq_row(xr);
        float bd = -3.4e38f;
        int bi = 0x7FFFFFFF;
        for (int c = 0; c < KCB; c++) {
            const float* e = g_Eq + (size_t)c * DIM;
            float dot = 0.0f;
            for (int d = 0; d < DIM; d++)
                dot = __fmaf_rn(xr[d], e[d], dot);
            float c3 = qt(__fmul_rn(qt(dot), 2.0f));
            float S  = qt(__fadd_rn(xsq, g_esq[c]));
            float dist = -qt(__fsub_rn(S, c3));
            if (dist > bd) { bd = dist; bi = c; }
        }
        g_ind[row] = bi;
    }
}

// ---------------------------------------------------------------------------
// k_scatter: quantize gather + segment-sum atomics + ind output
// ---------------------------------------------------------------------------
__global__ __launch_bounds__(256)
void k_scatter(const float* __restrict__ x,
               const float* __restrict__ embed,
               float* __restrict__ out_q,
               float* __restrict__ out_ind) {
    int w = (blockIdx.x * blockDim.x + threadIdx.x) >> 5;
    int lane = threadIdx.x & 31;
    int ind = g_ind[w];

    float4 e4 = ((const float4*)(embed + (size_t)ind * DIM))[lane];
    ((float4*)(out_q + (size_t)w * DIM))[lane] = e4;

    float4 x4 = ((const float4*)(x + (size_t)w * DIM))[lane];
    float* dst = g_sum + (size_t)ind * DIM + lane * 4;
    atomicAdd(dst + 0, x4.x);
    atomicAdd(dst + 1, x4.y);
    atomicAdd(dst + 2, x4.z);
    atomicAdd(dst + 3, x4.w);
    if (lane == 0) {
        atomicAdd(&g_counts[ind], 1.0f);
        out_ind[w] = (float)ind;
    }
}

// ---------------------------------------------------------------------------
__global__ void k_total(const float* __restrict__ cs, float* __restrict__ out_ncs) {
    __shared__ float ws[32];
    int tid = threadIdx.x;
    float v = __fadd_rn(__fmul_rn(cs[tid], 0.99f),
                        __fmul_rn(0.01f, g_counts[tid]));
    out_ncs[tid] = v;
    float s = v;
    #pragma unroll
    for (int off = 16; off; off >>= 1)
        s += __shfl_xor_sync(0xffffffffu, s, off);
    if ((tid & 31) == 0) ws[tid >> 5] = s;
    __syncthreads();
    if (tid < 32) {
        float t = ws[tid];
        #pragma unroll
        for (int off = 16; off; off >>= 1)
            t += __shfl_xor_sync(0xffffffffu, t, off);
        if (tid == 0) ws[0] = t;
    }
    __syncthreads();
    float total = ws[0];
    g_smoothed[tid] = __fmul_rn(
        __fdiv_rn(__fadd_rn(v, 1e-5f), __fadd_rn(total, 0.01024f)), total);
}

__global__ void k_embed(const float* __restrict__ ea,
                        float* __restrict__ out_nea,
                        float* __restrict__ out_ne) {
    int i = (blockIdx.x * blockDim.x + threadIdx.x) * 4;
    float s = g_smoothed[i >> 7];
    float4 a = *(const float4*)&ea[i];
    float4 g = *(const float4*)&g_sum[i];
    float4 r, o;
    r.x = __fadd_rn(__fmul_rn(a.x, 0.99f), __fmul_rn(0.01f, g.x));
    r.y = __fadd_rn(__fmul_rn(a.y, 0.99f), __fmul_rn(0.01f, g.y));
    r.z = __fadd_rn(__fmul_rn(a.z, 0.99f), __fmul_rn(0.01f, g.z));
    r.w = __fadd_rn(__fmul_rn(a.w, 0.99f), __fmul_rn(0.01f, g.w));
    *(float4*)&out_nea[i] = r;
    o.x = __fdiv_rn(r.x, s); o.y = __fdiv_rn(r.y, s);
    o.z = __fdiv_rn(r.z, s); o.w = __fdiv_rn(r.w, s);
    *(float4*)&out_ne[i] = o;
}

// ---------------------------------------------------------------------------
extern "C" void kernel_launch(void* const* d_in, const int* in_sizes, int n_in,
                              void* d_out, int out_size) {
    const float* x     = (const float*)d_in[0];
    const float* embed = (const float*)d_in[1];
    const float* cs    = (const float*)d_in[2];
    const float* ea    = (const float*)d_in[3];

    float* out     = (float*)d_out;
    float* out_q   = out;
    float* out_ind = out + (size_t)N_ROWS * DIM;
    float* out_ncs = out_ind + N_ROWS;
    float* out_nea = out_ncs + KCB;
    float* out_ne  = out_nea + (size_t)KCB * DIM;

    static bool attr_done = false;
    if (!attr_done) {
        cudaFuncSetAttribute(k_main, cudaFuncAttributeMaxDynamicSharedMemorySize,
                             SMEM_BYTES);
        attr_done = true;
    }

    k_pre<<<KCB, DIM>>>(embed);
    k_esq<<<KCB / 128, 128>>>(embed);
    k_main<<<N_ROWS / BM, 256, SMEM_BYTES>>>(x);
    k_fix<<<N_ROWS / 256, 256>>>(x);
    k_scatter<<<(N_ROWS * 32) / 256, 256>>>(x, embed, out_q, out_ind);
    k_total<<<1, 1024>>>(cs, out_ncs);
    k_embed<<<(KCB * DIM) / (256 * 4), 256>>>(ea, out_nea, out_ne);
}

// round 8
// speedup vs baseline: 3.7262x; 1.0941x over previous
#include <cuda_runtime.h>
#include <cuda_bf16.h>
#include <cstdint>

#define N_ROWS 131072
#define DIM 128
#define KCB 1024
#define BM 128
#define PRECF 1e7f
#define NCAND 16
#define MARGIN 6e-2f
#define FIXMARGIN 4.5e-2f

// padded row: 128 bf16 = 256B + 16B pad = 272B (conflict-free ldmatrix)
#define ROWB 272
#define TILEB (BM * ROWB)          // 34816 bytes: one 128x128 bf16 tile

// smem layout
#define SM_XH  0
#define SM_XL  TILEB
#define SM_E   (2 * TILEB)                 // + buf*TILEB, 2 buffers (hi only)
#define SM_ESQ (4 * TILEB)                 // 1024 floats
#define SM_CNT (SM_ESQ + 4096)             // 128 ints
#define SMEM_BYTES (SM_CNT + 512)          // 143872

// ---- device scratch ----
__device__ int     g_ind[N_ROWS];
__device__ float   g_esq[KCB];
__device__ float   g_Eq[KCB * DIM];          // qt(E), natural layout (k_fix)
__device__ uint8_t g_Ehi[8 * TILEB];         // per chunk: bf16-hi tile, padded
__device__ int2    g_cand[(size_t)N_ROWS * NCAND];
__device__ int     g_ncand[N_ROWS];
__device__ float   g_counts[KCB];
__device__ float   g_sum[KCB * DIM];
__device__ float   g_smoothed[KCB];

__device__ __forceinline__ float qt(float t) {
    return __fdiv_rn(rintf(__fmul_rn(t, PRECF)), PRECF);
}
__device__ __forceinline__ uint32_t smem_u32(const void* p) {
    return (uint32_t)__cvta_generic_to_shared(p);
}
__device__ __forceinline__ void cp16(uint32_t dst, const void* src) {
    asm volatile("cp.async.cg.shared.global [%0], [%1], 16;" :: "r"(dst), "l"(src));
}
__device__ __forceinline__ void cp_commit() { asm volatile("cp.async.commit_group;"); }
template <int N>
__device__ __forceinline__ void cp_wait() {
    asm volatile("cp.async.wait_group %0;" :: "n"(N));
}
__device__ __forceinline__ void ldsm4(uint32_t* r, uint32_t addr) {
    asm volatile("ldmatrix.sync.aligned.m8n8.x4.shared.b16 {%0,%1,%2,%3},[%4];"
                 : "=r"(r[0]), "=r"(r[1]), "=r"(r[2]), "=r"(r[3]) : "r"(addr));
}
__device__ __forceinline__ void mma_bf16(float* d, const uint32_t* a,
                                         uint32_t b0, uint32_t b1) {
    asm volatile(
        "mma.sync.aligned.m16n8k16.row.col.f32.bf16.bf16.f32 "
        "{%0,%1,%2,%3},{%4,%5,%6,%7},{%8,%9},{%0,%1,%2,%3};"
        : "+f"(d[0]), "+f"(d[1]), "+f"(d[2]), "+f"(d[3])
        : "r"(a[0]), "r"(a[1]), "r"(a[2]), "r"(a[3]), "r"(b0), "r"(b1));
}

// exact R4 GPU-shape x_sq over one 128-float row
__device__ float xsq_row(const float* __restrict__ v) {
    float s[32];
    #pragma unroll
    for (int t = 0; t < 32; t++) {
        float a0 = v[2 * t], a1 = v[2 * t + 1];
        float b0 = v[64 + 2 * t], b1 = v[64 + 2 * t + 1];
        float p0 = __fmaf_rn(b0, b0, __fmaf_rn(a0, a0, 0.0f));
        float p1 = __fmaf_rn(b1, b1, __fmaf_rn(a1, a1, 0.0f));
        s[t] = __fadd_rn(p0, p1);
    }
    #pragma unroll
    for (int off = 16; off; off >>= 1)
        #pragma unroll
        for (int t = 0; t < off; t++)
            s[t] = __fadd_rn(s[t], s[t + off]);
    return qt(s[0]);
}

// ---------------------------------------------------------------------------
// k_pre: qt(E); bf16-hi into padded chunk tiles; zero accums
// ---------------------------------------------------------------------------
__global__ void k_pre(const float* __restrict__ embed) {
    int k = blockIdx.x;
    int d = threadIdx.x;
    float eq = qt(embed[k * DIM + d]);
    g_Eq[k * DIM + d] = eq;
    int chunk = k >> 7, c = k & 127;
    *(__nv_bfloat16*)(g_Ehi + (size_t)chunk * TILEB + c * ROWB + d * 2) =
        __float2bfloat16(eq);
    g_sum[k * DIM + d] = 0.0f;
    if (d == 0) g_counts[k] = 0.0f;
}

// ---------------------------------------------------------------------------
// k_esq: XLA:GPU column-reduction emulation (bit-exact, proven R4)
// ---------------------------------------------------------------------------
__global__ void k_esq(const float* __restrict__ embed) {
    int k = blockIdx.x * 128 + threadIdx.x;
    const float* row = embed + (size_t)k * DIM;
    float s[32];
    #pragma unroll
    for (int j = 0; j < 32; j++) {
        float p = 0.0f;
        #pragma unroll
        for (int i = 0; i < 4; i++) {
            float e = qt(row[j + 32 * i]);
            p = __fmaf_rn(e, e, p);
        }
        s[j] = p;
    }
    #pragma unroll
    for (int off = 16; off; off >>= 1)
        #pragma unroll
        for (int t = 0; t < off; t++)
            s[t] = __fadd_rn(s[t], s[t + off]);
    g_esq[k] = qt(s[0]);
}

// ---------------------------------------------------------------------------
// k_main: HMMA bf16 2-term screen (x_hi+x_lo vs e_hi) + in-register argmax
// 256 threads = 8 warps, warp w owns rows w*16..w*16+15 x all codes
// ---------------------------------------------------------------------------
__global__ __launch_bounds__(256, 1)
void k_main(const float* __restrict__ x) {
    extern __shared__ char smem[];
    uint32_t sb = smem_u32(smem);
    float* esq_s = (float*)(smem + SM_ESQ);
    int*   cnt_s = (int*)(smem + SM_CNT);

    int tid = threadIdx.x;
    int warp = tid >> 5;
    int lane = tid & 31;
    int g = lane >> 2, tig = lane & 3;
    int row0 = blockIdx.x * BM;

    if (tid < BM) cnt_s[tid] = 0;

    // prefetch E chunks 0 and 1 (hi tiles only): 2*2176 = 4352 granules
    #pragma unroll
    for (int b = 0; b < 2; b++) {
        #pragma unroll
        for (int s = 0; s < 9; s++) {
            int gr = tid + s * 256;
            if (gr < TILEB / 16)
                cp16(sb + SM_E + b * TILEB + gr * 16,
                     g_Ehi + (size_t)b * TILEB + gr * 16);
        }
        cp_commit();
    }

    // X load + bf16 hi/lo split into padded tiles
    #pragma unroll
    for (int s = 0; s < 32; s++) {
        int p = tid + s * 256;                 // 8192 pairs
        int row = p >> 6, d = (p & 63) * 2;
        float2 v = *(const float2*)(x + (size_t)(row0 + row) * DIM + d);
        __nv_bfloat16 h0 = __float2bfloat16(v.x);
        __nv_bfloat16 h1 = __float2bfloat16(v.y);
        __nv_bfloat16 l0 = __float2bfloat16(__fsub_rn(v.x, __bfloat162float(h0)));
        __nv_bfloat16 l1 = __float2bfloat16(__fsub_rn(v.y, __bfloat162float(h1)));
        *(__nv_bfloat162*)(smem + SM_XH + row * ROWB + d * 2) = __nv_bfloat162(h0, h1);
        *(__nv_bfloat162*)(smem + SM_XL + row * ROWB + d * 2) = __nv_bfloat162(l0, l1);
    }
    #pragma unroll
    for (int s = 0; s < 4; s++) esq_s[tid + s * 256] = g_esq[tid + s * 256];
    __syncthreads();

    // A fragments (X hi/lo), resident for all chunks: 8 ksteps x 4 regs each
    uint32_t ah[8][4], al[8][4];
    {
        uint32_t abase = sb + SM_XH + (warp * 16 + (lane & 15)) * ROWB
                       + (lane >> 4) * 16;
        #pragma unroll
        for (int s = 0; s < 8; s++) {
            ldsm4(ah[s], abase + s * 32);
            ldsm4(al[s], abase + TILEB + s * 32);
        }
    }

    float bestA = -3.4e38f, bestB = -3.4e38f;
    int rowA = warp * 16 + g, rowB = rowA + 8;

    for (int kc = 0; kc < 8; kc++) {
        if (kc < 7) cp_wait<1>(); else cp_wait<0>();
        __syncthreads();
        uint32_t eb = sb + SM_E + (kc & 1) * TILEB;

        #pragma unroll
        for (int h = 0; h < 2; h++) {          // 64 codes per half
            float acc[8][4];
            #pragma unroll
            for (int n = 0; n < 8; n++)
                #pragma unroll
                for (int j = 0; j < 4; j++) acc[n][j] = 0.0f;

            #pragma unroll
            for (int pp = 0; pp < 2; pp++) {   // 32-code block: 4 ntiles
                int nt0 = pp * 4;
                uint32_t b0a = eb + (uint32_t)((h * 64 + pp * 32 + (lane & 7)
                                 + ((lane & 16) ? 8 : 0)) * ROWB)
                             + ((lane >> 3) & 1) * 16;
                uint32_t b1a = b0a + 16 * ROWB;
                #pragma unroll
                for (int s = 0; s < 8; s++) {
                    uint32_t bh0[4], bh1[4];
                    ldsm4(bh0, b0a + s * 32);
                    ldsm4(bh1, b1a + s * 32);
                    mma_bf16(acc[nt0 + 0], ah[s], bh0[0], bh0[1]);
                    mma_bf16(acc[nt0 + 1], ah[s], bh0[2], bh0[3]);
                    mma_bf16(acc[nt0 + 2], ah[s], bh1[0], bh1[1]);
                    mma_bf16(acc[nt0 + 3], ah[s], bh1[2], bh1[3]);
                    mma_bf16(acc[nt0 + 0], al[s], bh0[0], bh0[1]);
                    mma_bf16(acc[nt0 + 1], al[s], bh0[2], bh0[3]);
                    mma_bf16(acc[nt0 + 2], al[s], bh1[0], bh1[1]);
                    mma_bf16(acc[nt0 + 3], al[s], bh1[2], bh1[3]);
                }
            }

            // epilogue: scores, quad row max, candidate collection
            float mA = -3.4e38f, mB = -3.4e38f;
            #pragma unroll
            for (int nt = 0; nt < 8; nt++) {
                int c = kc * 128 + h * 64 + nt * 8 + tig * 2;
                float e0 = esq_s[c], e1 = esq_s[c + 1];
                acc[nt][0] = __fmaf_rn(2.0f, acc[nt][0], -e0);
                acc[nt][1] = __fmaf_rn(2.0f, acc[nt][1], -e1);
                acc[nt][2] = __fmaf_rn(2.0f, acc[nt][2], -e0);
                acc[nt][3] = __fmaf_rn(2.0f, acc[nt][3], -e1);
                mA = fmaxf(mA, fmaxf(acc[nt][0], acc[nt][1]));
                mB = fmaxf(mB, fmaxf(acc[nt][2], acc[nt][3]));
            }
            mA = fmaxf(mA, __shfl_xor_sync(0xffffffffu, mA, 1));
            mA = fmaxf(mA, __shfl_xor_sync(0xffffffffu, mA, 2));
            mB = fmaxf(mB, __shfl_xor_sync(0xffffffffu, mB, 1));
            mB = fmaxf(mB, __shfl_xor_sync(0xffffffffu, mB, 2));
            bestA = fmaxf(bestA, mA);
            bestB = fmaxf(bestB, mB);
            float thrA = bestA - MARGIN, thrB = bestB - MARGIN;

            #pragma unroll
            for (int nt = 0; nt < 8; nt++) {
                int c = kc * 128 + h * 64 + nt * 8 + tig * 2;
                #pragma unroll
                for (int j = 0; j < 4; j++) {
                    float sc = acc[nt][j];
                    bool isB = (j >= 2);
                    if (sc >= (isB ? thrB : thrA)) {
                        int r = isB ? rowB : rowA;
                        int slot = atomicAdd(&cnt_s[r], 1);
                        if (slot < NCAND)
                            g_cand[(size_t)(row0 + r) * NCAND + slot] =
                                make_int2(__float_as_int(sc), c + (j & 1));
                    }
                }
            }
        }

        __syncthreads();   // all warps done reading E buffer (kc&1)
        if (kc + 2 < 8) {
            #pragma unroll
            for (int s = 0; s < 9; s++) {
                int gr = tid + s * 256;
                if (gr < TILEB / 16)
                    cp16(sb + SM_E + (kc & 1) * TILEB + gr * 16,
                         g_Ehi + (size_t)(kc + 2) * TILEB + gr * 16);
            }
            cp_commit();
        }
    }

    __syncthreads();
    if (tid < BM) g_ncand[row0 + tid] = cnt_s[tid];
}

// ---------------------------------------------------------------------------
// k_fix: final decision. 1 qualifier -> done; else bit-exact R4 chain.
// Overflowed candidate list -> full exact scan.
// ---------------------------------------------------------------------------
__global__ void k_fix(const float* __restrict__ x) {
    int row = blockIdx.x * 256 + threadIdx.x;
    int n = g_ncand[row];
    const float* xr = x + (size_t)row * DIM;

    if (n <= NCAND) {
        const int2* cand = &g_cand[(size_t)row * NCAND];
        float mr = -3.4e38f;
        for (int s = 0; s < n; s++)
            mr = fmaxf(mr, __int_as_float(cand[s].x));
        float thr = mr - FIXMARGIN;

        int nq = 0, only = 0;
        for (int s = 0; s < n; s++)
            if (__int_as_float(cand[s].x) >= thr) { nq++; only = cand[s].y; }
        if (nq <= 1) { g_ind[row] = only; return; }

        float xsq = xsq_row(xr);
        float bd = -3.4e38f;
        int bi = 0x7FFFFFFF;
        for (int s = 0; s < n; s++) {
            if (__int_as_float(cand[s].x) < thr) continue;
            int c = cand[s].y;
            const float* e = g_Eq + (size_t)c * DIM;
            float dot = 0.0f;
            for (int d = 0; d < DIM; d++)
                dot = __fmaf_rn(xr[d], e[d], dot);
            float c3 = qt(__fmul_rn(qt(dot), 2.0f));
            float S  = qt(__fadd_rn(xsq, g_esq[c]));
            float dist = -qt(__fsub_rn(S, c3));
            if (dist > bd || (dist == bd && c < bi)) { bd = dist; bi = c; }
        }
        g_ind[row] = bi;
    } else {
        float xsq = xsq_row(xr);
        float bd = -3.4e38f;
        int bi = 0x7FFFFFFF;
        for (int c = 0; c < KCB; c++) {
            const float* e = g_Eq + (size_t)c * DIM;
            float dot = 0.0f;
            for (int d = 0; d < DIM; d++)
                dot = __fmaf_rn(xr[d], e[d], dot);
            float c3 = qt(__fmul_rn(qt(dot), 2.0f));
            float S  = qt(__fadd_rn(xsq, g_esq[c]));
            float dist = -qt(__fsub_rn(S, c3));
            if (dist > bd) { bd = dist; bi = c; }
        }
        g_ind[row] = bi;
    }
}

// ---------------------------------------------------------------------------
// k_scatter: quantize gather + segment-sum atomics + ind output
// ---------------------------------------------------------------------------
__global__ __launch_bounds__(256)
void k_scatter(const float* __restrict__ x,
               const float* __restrict__ embed,
               float* __restrict__ out_q,
               float* __restrict__ out_ind) {
    int w = (blockIdx.x * blockDim.x + threadIdx.x) >> 5;
    int lane = threadIdx.x & 31;
    int ind = g_ind[w];

    float4 e4 = ((const float4*)(embed + (size_t)ind * DIM))[lane];
    ((float4*)(out_q + (size_t)w * DIM))[lane] = e4;

    float4 x4 = ((const float4*)(x + (size_t)w * DIM))[lane];
    float* dst = g_sum + (size_t)ind * DIM + lane * 4;
    atomicAdd(dst + 0, x4.x);
    atomicAdd(dst + 1, x4.y);
    atomicAdd(dst + 2, x4.z);
    atomicAdd(dst + 3, x4.w);
    if (lane == 0) {
        atomicAdd(&g_counts[ind], 1.0f);
        out_ind[w] = (float)ind;
    }
}

// ---------------------------------------------------------------------------
__global__ void k_total(const float* __restrict__ cs, float* __restrict__ out_ncs) {
    __shared__ float ws[32];
    int tid = threadIdx.x;
    float v = __fadd_rn(__fmul_rn(cs[tid], 0.99f),
                        __fmul_rn(0.01f, g_counts[tid]));
    out_ncs[tid] = v;
    float s = v;
    #pragma unroll
    for (int off = 16; off; off >>= 1)
        s += __shfl_xor_sync(0xffffffffu, s, off);
    if ((tid & 31) == 0) ws[tid >> 5] = s;
    __syncthreads();
    if (tid < 32) {
        float t = ws[tid];
        #pragma unroll
        for (int off = 16; off; off >>= 1)
            t += __shfl_xor_sync(0xffffffffu, t, off);
        if (tid == 0) ws[0] = t;
    }
    __syncthreads();
    float total = ws[0];
    g_smoothed[tid] = __fmul_rn(
        __fdiv_rn(__fadd_rn(v, 1e-5f), __fadd_rn(total, 0.01024f)), total);
}

__global__ void k_embed(const float* __restrict__ ea,
                        float* __restrict__ out_nea,
                        float* __restrict__ out_ne) {
    int i = (blockIdx.x * blockDim.x + threadIdx.x) * 4;
    float s = g_smoothed[i >> 7];
    float4 a = *(const float4*)&ea[i];
    float4 g = *(const float4*)&g_sum[i];
    float4 r, o;
    r.x = __fadd_rn(__fmul_rn(a.x, 0.99f), __fmul_rn(0.01f, g.x));
    r.y = __fadd_rn(__fmul_rn(a.y, 0.99f), __fmul_rn(0.01f, g.y));
    r.z = __fadd_rn(__fmul_rn(a.z, 0.99f), __fmul_rn(0.01f, g.z));
    r.w = __fadd_rn(__fmul_rn(a.w, 0.99f), __fmul_rn(0.01f, g.w));
    *(float4*)&out_nea[i] = r;
    o.x = __fdiv_rn(r.x, s); o.y = __fdiv_rn(r.y, s);
    o.z = __fdiv_rn(r.z, s); o.w = __fdiv_rn(r.w, s);
    *(float4*)&out_ne[i] = o;
}

// ---------------------------------------------------------------------------
extern "C" void kernel_launch(void* const* d_in, const int* in_sizes, int n_in,
                              void* d_out, int out_size) {
    const float* x     = (const float*)d_in[0];
    const float* embed = (const float*)d_in[1];
    const float* cs    = (const float*)d_in[2];
    const float* ea    = (const float*)d_in[3];

    float* out     = (float*)d_out;
    float* out_q   = out;
    float* out_ind = out + (size_t)N_ROWS * DIM;
    float* out_ncs = out_ind + N_ROWS;
    float* out_nea = out_ncs + KCB;
    float* out_ne  = out_nea + (size_t)KCB * DIM;

    static bool attr_done = false;
    if (!attr_done) {
        cudaFuncSetAttribute(k_main, cudaFuncAttributeMaxDynamicSharedMemorySize,
                             SMEM_BYTES);
        attr_done = true;
    }

    k_pre<<<KCB, DIM>>>(embed);
    k_esq<<<KCB / 128, 128>>>(embed);
    k_main<<<N_ROWS / BM, 256, SMEM_BYTES>>>(x);
    k_fix<<<N_ROWS / 256, 256>>>(x);
    k_scatter<<<(N_ROWS * 32) / 256, 256>>>(x, embed, out_q, out_ind);
    k_total<<<1, 1024>>>(cs, out_ncs);
    k_embed<<<(KCB * DIM) / (256 * 4), 256>>>(ea, out_nea, out_ne);
}

// round 9
// speedup vs baseline: 5.9793x; 1.6047x over previous
#include <cuda_runtime.h>
#include <cuda_bf16.h>
#include <cstdint>

#define N_ROWS 131072
#define DIM 128
#define KCB 1024
#define BM 128
#define PRECF 1e7f
#define NCAND 16
#define MARGIN 6e-2f
#define FIXMARGIN 4.5e-2f

// padded row: 128 bf16 = 256B + 16B pad = 272B (conflict-free ldmatrix)
#define ROWB 272
#define TILEB (BM * ROWB)          // 34816 bytes: one 128x128 bf16 tile

// smem layout (109056 total -> 2 CTAs/SM)
#define SM_XH  0
#define SM_E   TILEB                       // + buf*TILEB, 2 buffers
#define SM_ESQ (3 * TILEB)                 // 1024 floats
#define SM_CNT (SM_ESQ + 4096)             // 128 ints
#define SMEM_BYTES (SM_CNT + 512)          // 109056

// ---- device scratch ----
__device__ int     g_ind[N_ROWS];
__device__ float   g_esq[KCB];
__device__ float   g_Eq[KCB * DIM];          // qt(E), natural layout (k_fix)
__device__ uint8_t g_Ehi[8 * TILEB];         // per chunk: bf16-hi tile, padded
__device__ int2    g_cand[(size_t)N_ROWS * NCAND];
__device__ int     g_ncand[N_ROWS];
__device__ int     g_work[N_ROWS];
__device__ int     g_nwork;
__device__ int     g_cnti[KCB];
__device__ int     g_off[KCB];
__device__ int     g_slot[N_ROWS];
__device__ int     g_rowlist[N_ROWS];
__device__ float   g_smoothed[KCB];

__device__ __forceinline__ float qt(float t) {
    return __fdiv_rn(rintf(__fmul_rn(t, PRECF)), PRECF);
}
__device__ __forceinline__ uint32_t smem_u32(const void* p) {
    return (uint32_t)__cvta_generic_to_shared(p);
}
__device__ __forceinline__ void cp16(uint32_t dst, const void* src) {
    asm volatile("cp.async.cg.shared.global [%0], [%1], 16;" :: "r"(dst), "l"(src));
}
__device__ __forceinline__ void cp_commit() { asm volatile("cp.async.commit_group;"); }
template <int N>
__device__ __forceinline__ void cp_wait() {
    asm volatile("cp.async.wait_group %0;" :: "n"(N));
}
__device__ __forceinline__ void ldsm4(uint32_t* r, uint32_t addr) {
    asm volatile("ldmatrix.sync.aligned.m8n8.x4.shared.b16 {%0,%1,%2,%3},[%4];"
                 : "=r"(r[0]), "=r"(r[1]), "=r"(r[2]), "=r"(r[3]) : "r"(addr));
}
__device__ __forceinline__ void mma_bf16(float* d, const uint32_t* a,
                                         uint32_t b0, uint32_t b1) {
    asm volatile(
        "mma.sync.aligned.m16n8k16.row.col.f32.bf16.bf16.f32 "
        "{%0,%1,%2,%3},{%4,%5,%6,%7},{%8,%9},{%0,%1,%2,%3};"
        : "+f"(d[0]), "+f"(d[1]), "+f"(d[2]), "+f"(d[3])
        : "r"(a[0]), "r"(a[1]), "r"(a[2]), "r"(a[3]), "r"(b0), "r"(b1));
}

// exact R4 GPU-shape x_sq over one 128-float row
__device__ float xsq_row(const float* __restrict__ v) {
    float s[32];
    #pragma unroll
    for (int t = 0; t < 32; t++) {
        float a0 = v[2 * t], a1 = v[2 * t + 1];
        float b0 = v[64 + 2 * t], b1 = v[64 + 2 * t + 1];
        float p0 = __fmaf_rn(b0, b0, __fmaf_rn(a0, a0, 0.0f));
        float p1 = __fmaf_rn(b1, b1, __fmaf_rn(a1, a1, 0.0f));
        s[t] = __fadd_rn(p0, p1);
    }
    #pragma unroll
    for (int off = 16; off; off >>= 1)
        #pragma unroll
        for (int t = 0; t < off; t++)
            s[t] = __fadd_rn(s[t], s[t + off]);
    return qt(s[0]);
}

// exact dist for one (row, code): bit-identical to the R4 chain
__device__ __forceinline__ float exact_dist(const float* __restrict__ xr,
                                            float xsq, int c) {
    const float* e = g_Eq + (size_t)c * DIM;
    float dot = 0.0f;
    #pragma unroll 8
    for (int d = 0; d < DIM; d++)
        dot = __fmaf_rn(xr[d], e[d], dot);
    float c3 = qt(__fmul_rn(qt(dot), 2.0f));
    float S  = qt(__fadd_rn(xsq, g_esq[c]));
    return -qt(__fsub_rn(S, c3));
}

// ---------------------------------------------------------------------------
// k_pre: qt(E); bf16-hi into padded chunk tiles; zero counters
// ---------------------------------------------------------------------------
__global__ void k_pre(const float* __restrict__ embed) {
    int k = blockIdx.x;
    int d = threadIdx.x;
    float eq = qt(embed[k * DIM + d]);
    g_Eq[k * DIM + d] = eq;
    int chunk = k >> 7, c = k & 127;
    *(__nv_bfloat16*)(g_Ehi + (size_t)chunk * TILEB + c * ROWB + d * 2) =
        __float2bfloat16(eq);
    if (d == 0) {
        g_cnti[k] = 0;
        if (k == 0) g_nwork = 0;
    }
}

// ---------------------------------------------------------------------------
// k_esq: XLA:GPU column-reduction emulation (bit-exact, proven R4)
// ---------------------------------------------------------------------------
__global__ void k_esq(const float* __restrict__ embed) {
    int k = blockIdx.x * 128 + threadIdx.x;
    const float* row = embed + (size_t)k * DIM;
    float s[32];
    #pragma unroll
    for (int j = 0; j < 32; j++) {
        float p = 0.0f;
        #pragma unroll
        for (int i = 0; i < 4; i++) {
            float e = qt(row[j + 32 * i]);
            p = __fmaf_rn(e, e, p);
        }
        s[j] = p;
    }
    #pragma unroll
    for (int off = 16; off; off >>= 1)
        #pragma unroll
        for (int t = 0; t < off; t++)
            s[t] = __fadd_rn(s[t], s[t + off]);
    g_esq[k] = qt(s[0]);
}

// ---------------------------------------------------------------------------
// k_main: HMMA bf16 1-term screen (bf16(x)·bf16(e)) + in-register argmax
// 256 threads = 8 warps, warp w owns rows w*16..w*16+15 x all codes
// ---------------------------------------------------------------------------
__global__ __launch_bounds__(256, 2)
void k_main(const float* __restrict__ x) {
    extern __shared__ char smem[];
    uint32_t sb = smem_u32(smem);
    float* esq_s = (float*)(smem + SM_ESQ);
    int*   cnt_s = (int*)(smem + SM_CNT);

    int tid = threadIdx.x;
    int warp = tid >> 5;
    int lane = tid & 31;
    int g = lane >> 2, tig = lane & 3;
    int row0 = blockIdx.x * BM;

    if (tid < BM) cnt_s[tid] = 0;

    // prefetch E chunks 0 and 1
    #pragma unroll
    for (int b = 0; b < 2; b++) {
        #pragma unroll
        for (int s = 0; s < 9; s++) {
            int gr = tid + s * 256;
            if (gr < TILEB / 16)
                cp16(sb + SM_E + b * TILEB + gr * 16,
                     g_Ehi + (size_t)b * TILEB + gr * 16);
        }
        cp_commit();
    }

    // X load -> bf16 hi tile
    #pragma unroll
    for (int s = 0; s < 32; s++) {
        int p = tid + s * 256;                 // 8192 pairs
        int row = p >> 6, d = (p & 63) * 2;
        float2 v = *(const float2*)(x + (size_t)(row0 + row) * DIM + d);
        *(__nv_bfloat162*)(smem + SM_XH + row * ROWB + d * 2) =
            __nv_bfloat162(__float2bfloat16(v.x), __float2bfloat16(v.y));
    }
    #pragma unroll
    for (int s = 0; s < 4; s++) esq_s[tid + s * 256] = g_esq[tid + s * 256];
    __syncthreads();

    // A fragments (X hi), resident for all chunks: 8 ksteps x 4 regs
    uint32_t ah[8][4];
    {
        uint32_t abase = sb + SM_XH + (warp * 16 + (lane & 15)) * ROWB
                       + (lane >> 4) * 16;
        #pragma unroll
        for (int s = 0; s < 8; s++) ldsm4(ah[s], abase + s * 32);
    }

    float bestA = -3.4e38f, bestB = -3.4e38f;
    int rowA = warp * 16 + g, rowB = rowA + 8;

    for (int kc = 0; kc < 8; kc++) {
        if (kc < 7) cp_wait<1>(); else cp_wait<0>();
        __syncthreads();
        uint32_t eb = sb + SM_E + (kc & 1) * TILEB;

        #pragma unroll
        for (int h = 0; h < 2; h++) {          // 64 codes per half
            float acc[8][4];
            #pragma unroll
            for (int n = 0; n < 8; n++)
                #pragma unroll
                for (int j = 0; j < 4; j++) acc[n][j] = 0.0f;

            #pragma unroll
            for (int pp = 0; pp < 2; pp++) {
                int nt0 = pp * 4;
                uint32_t b0a = eb + (uint32_t)((h * 64 + pp * 32 + (lane & 7)
                                 + ((lane & 16) ? 8 : 0)) * ROWB)
                             + ((lane >> 3) & 1) * 16;
                uint32_t b1a = b0a + 16 * ROWB;
                #pragma unroll
                for (int s = 0; s < 8; s++) {
                    uint32_t bh0[4], bh1[4];
                    ldsm4(bh0, b0a + s * 32);
                    ldsm4(bh1, b1a + s * 32);
                    mma_bf16(acc[nt0 + 0], ah[s], bh0[0], bh0[1]);
                    mma_bf16(acc[nt0 + 1], ah[s], bh0[2], bh0[3]);
                    mma_bf16(acc[nt0 + 2], ah[s], bh1[0], bh1[1]);
                    mma_bf16(acc[nt0 + 3], ah[s], bh1[2], bh1[3]);
                }
            }

            // epilogue: scores, quad row max, candidate collection
            float mA = -3.4e38f, mB = -3.4e38f;
            #pragma unroll
            for (int nt = 0; nt < 8; nt++) {
                int c = kc * 128 + h * 64 + nt * 8 + tig * 2;
                float e0 = esq_s[c], e1 = esq_s[c + 1];
                acc[nt][0] = __fmaf_rn(2.0f, acc[nt][0], -e0);
                acc[nt][1] = __fmaf_rn(2.0f, acc[nt][1], -e1);
                acc[nt][2] = __fmaf_rn(2.0f, acc[nt][2], -e0);
                acc[nt][3] = __fmaf_rn(2.0f, acc[nt][3], -e1);
                mA = fmaxf(mA, fmaxf(acc[nt][0], acc[nt][1]));
                mB = fmaxf(mB, fmaxf(acc[nt][2], acc[nt][3]));
            }
            mA = fmaxf(mA, __shfl_xor_sync(0xffffffffu, mA, 1));
            mA = fmaxf(mA, __shfl_xor_sync(0xffffffffu, mA, 2));
            mB = fmaxf(mB, __shfl_xor_sync(0xffffffffu, mB, 1));
            mB = fmaxf(mB, __shfl_xor_sync(0xffffffffu, mB, 2));
            bestA = fmaxf(bestA, mA);
            bestB = fmaxf(bestB, mB);
            float thrA = bestA - MARGIN, thrB = bestB - MARGIN;

            #pragma unroll
            for (int nt = 0; nt < 8; nt++) {
                int c = kc * 128 + h * 64 + nt * 8 + tig * 2;
                #pragma unroll
                for (int j = 0; j < 4; j++) {
                    float sc = acc[nt][j];
                    bool isB = (j >= 2);
                    if (sc >= (isB ? thrB : thrA)) {
                        int r = isB ? rowB : rowA;
                        int slot = atomicAdd(&cnt_s[r], 1);
                        if (slot < NCAND)
                            g_cand[(size_t)(row0 + r) * NCAND + slot] =
                                make_int2(__float_as_int(sc), c + (j & 1));
                    }
                }
            }
        }

        __syncthreads();
        if (kc + 2 < 8) {
            #pragma unroll
            for (int s = 0; s < 9; s++) {
                int gr = tid + s * 256;
                if (gr < TILEB / 16)
                    cp16(sb + SM_E + (kc & 1) * TILEB + gr * 16,
                         g_Ehi + (size_t)(kc + 2) * TILEB + gr * 16);
            }
            cp_commit();
        }
    }

    __syncthreads();
    if (tid < BM) g_ncand[row0 + tid] = cnt_s[tid];
}

// ---------------------------------------------------------------------------
// k_fix1: resolve single-qualifier rows; push the rest to the worklist
// ---------------------------------------------------------------------------
__global__ void k_fix1() {
    int row = blockIdx.x * 256 + threadIdx.x;
    int n = g_ncand[row];
    if (n <= NCAND) {
        const int2* cand = &g_cand[(size_t)row * NCAND];
        float mr = -3.4e38f;
        for (int s = 0; s < n; s++)
            mr = fmaxf(mr, __int_as_float(cand[s].x));
        float thr = mr - FIXMARGIN;
        int nq = 0, only = 0;
        for (int s = 0; s < n; s++)
            if (__int_as_float(cand[s].x) >= thr) { nq++; only = cand[s].y; }
        if (nq <= 1) { g_ind[row] = only; return; }
    }
    int w = atomicAdd(&g_nwork, 1);
    g_work[w] = row;
}

// ---------------------------------------------------------------------------
// k_fix2: warp per work-row; lane per candidate, bit-exact R4 chain
// ---------------------------------------------------------------------------
__global__ __launch_bounds__(256)
void k_fix2(const float* __restrict__ x) {
    int gw = (blockIdx.x * 256 + threadIdx.x) >> 5;
    int lane = threadIdx.x & 31;
    int nwarps = gridDim.x * 8;
    int nwork = g_nwork;

    for (int i = gw; i < nwork; i += nwarps) {
        int row = g_work[i];
        const float* xr = x + (size_t)row * DIM;
        int n = g_ncand[row];
        float xsq = xsq_row(xr);           // uniform addresses -> broadcast

        float bd = -3.4e38f;
        int bi = 0x7FFFFFFF;
        if (n <= NCAND) {
            int2 cd = (lane < n) ? g_cand[(size_t)row * NCAND + lane]
                                 : make_int2((int)0xFF800000, 0x7FFFFFFF);
            float raw = __int_as_float(cd.x);
            float mr = raw;
            #pragma unroll
            for (int off = 16; off; off >>= 1)
                mr = fmaxf(mr, __shfl_xor_sync(0xffffffffu, mr, off));
            if (lane < n && raw >= mr - FIXMARGIN) {
                bd = exact_dist(xr, xsq, cd.y);
                bi = cd.y;
            }
        } else {
            for (int c = lane; c < KCB; c += 32) {
                float dist = exact_dist(xr, xsq, c);
                if (dist > bd) { bd = dist; bi = c; }  // ascending c per lane
            }
        }
        #pragma unroll
        for (int off = 16; off; off >>= 1) {
            float ov = __shfl_xor_sync(0xffffffffu, bd, off);
            int   oi = __shfl_xor_sync(0xffffffffu, bi, off);
            if (ov > bd || (ov == bd && oi < bi)) { bd = ov; bi = oi; }
        }
        if (lane == 0) g_ind[row] = bi;
    }
}

// ---------------------------------------------------------------------------
// k_hist: per-row slot assignment within its code bucket
// ---------------------------------------------------------------------------
__global__ void k_hist() {
    int row = blockIdx.x * 256 + threadIdx.x;
    g_slot[row] = atomicAdd(&g_cnti[g_ind[row]], 1);
}

// ---------------------------------------------------------------------------
// k_scan: prefix-sum of counts + ncs + smoothed (absorbs old k_total)
// ---------------------------------------------------------------------------
__global__ void k_scan(const float* __restrict__ cs, float* __restrict__ out_ncs) {
    __shared__ int sh[1024];
    __shared__ float ws[32];
    int tid = threadIdx.x;
    int c = g_cnti[tid];
    sh[tid] = c;
    __syncthreads();
    for (int off = 1; off < 1024; off <<= 1) {
        int t = (tid >= off) ? sh[tid - off] : 0;
        __syncthreads();
        sh[tid] += t;
        __syncthreads();
    }
    g_off[tid] = sh[tid] - c;

    float v = __fadd_rn(__fmul_rn(cs[tid], 0.99f), __fmul_rn(0.01f, (float)c));
    out_ncs[tid] = v;
    float s = v;
    #pragma unroll
    for (int off = 16; off; off >>= 1)
        s += __shfl_xor_sync(0xffffffffu, s, off);
    if ((tid & 31) == 0) ws[tid >> 5] = s;
    __syncthreads();
    if (tid < 32) {
        float t = ws[tid];
        #pragma unroll
        for (int off = 16; off; off >>= 1)
            t += __shfl_xor_sync(0xffffffffu, t, off);
        if (tid == 0) ws[0] = t;
    }
    __syncthreads();
    float total = ws[0];
    g_smoothed[tid] = __fmul_rn(
        __fdiv_rn(__fadd_rn(v, 1e-5f), __fadd_rn(total, 0.01024f)), total);
}

// ---------------------------------------------------------------------------
// k_place: scatter row indices into per-code buckets
// ---------------------------------------------------------------------------
__global__ void k_place() {
    int row = blockIdx.x * 256 + threadIdx.x;
    g_rowlist[g_off[g_ind[row]] + g_slot[row]] = row;
}

// ---------------------------------------------------------------------------
// k_gather: per-code x-sum (block=code, thread=dim) + nea + ne outputs
// ---------------------------------------------------------------------------
__global__ void k_gather(const float* __restrict__ x,
                         const float* __restrict__ ea,
                         float* __restrict__ out_nea,
                         float* __restrict__ out_ne) {
    __shared__ int rs[128];
    int k = blockIdx.x, d = threadIdx.x;
    int cnt = g_cnti[k], off = g_off[k];
    float s = 0.0f;
    for (int base = 0; base < cnt; base += 128) {
        int m = min(128, cnt - base);
        __syncthreads();
        if (d < m) rs[d] = g_rowlist[off + base + d];
        __syncthreads();
        for (int i = 0; i < m; i++)
            s += x[(size_t)rs[i] * DIM + d];
    }
    float r = __fadd_rn(__fmul_rn(ea[k * DIM + d], 0.99f), __fmul_rn(0.01f, s));
    out_nea[k * DIM + d] = r;
    out_ne[k * DIM + d] = __fdiv_rn(r, g_smoothed[k]);
}

// ---------------------------------------------------------------------------
// k_quant: pure gather for quantize + ind output (no atomics)
// ---------------------------------------------------------------------------
__global__ __launch_bounds__(256)
void k_quant(const float* __restrict__ embed,
             float* __restrict__ out_q,
             float* __restrict__ out_ind) {
    int w = (blockIdx.x * 256 + threadIdx.x) >> 5;
    int lane = threadIdx.x & 31;
    int ind = g_ind[w];
    float4 e4 = ((const float4*)(embed + (size_t)ind * DIM))[lane];
    ((float4*)(out_q + (size_t)w * DIM))[lane] = e4;
    if (lane == 0) out_ind[w] = (float)ind;
}

// ---------------------------------------------------------------------------
extern "C" void kernel_launch(void* const* d_in, const int* in_sizes, int n_in,
                              void* d_out, int out_size) {
    const float* x     = (const float*)d_in[0];
    const float* embed = (const float*)d_in[1];
    const float* cs    = (const float*)d_in[2];
    const float* ea    = (const float*)d_in[3];

    float* out     = (float*)d_out;
    float* out_q   = out;
    float* out_ind = out + (size_t)N_ROWS * DIM;
    float* out_ncs = out_ind + N_ROWS;
    float* out_nea = out_ncs + KCB;
    float* out_ne  = out_nea + (size_t)KCB * DIM;

    static bool attr_done = false;
    if (!attr_done) {
        cudaFuncSetAttribute(k_main, cudaFuncAttributeMaxDynamicSharedMemorySize,
                             SMEM_BYTES);
        attr_done = true;
    }

    k_pre<<<KCB, DIM>>>(embed);
    k_esq<<<KCB / 128, 128>>>(embed);
    k_main<<<N_ROWS / BM, 256, SMEM_BYTES>>>(x);
    k_fix1<<<N_ROWS / 256, 256>>>();
    k_fix2<<<296, 256>>>(x);
    k_hist<<<N_ROWS / 256, 256>>>();
    k_scan<<<1, 1024>>>(cs, out_ncs);
    k_place<<<N_ROWS / 256, 256>>>();
    k_gather<<<KCB, DIM>>>(x, ea, out_nea, out_ne);
    k_quant<<<(N_ROWS * 32) / 256, 256>>>(embed, out_q, out_ind);
}